// round 3
// baseline (speedup 1.0000x reference)
#include <cuda_runtime.h>

// Resample2d (FlowNet2 bilinear warp), fixed shape B=4, C=64, H=384, W=512.
//
// R2: merge the two x-taps of each row into ONE aligned float4 window load
// (row base y*W is 4-float aligned since W=512). Bilinear weights are folded
// into per-thread one-hot float4 weight vectors, so the channel loop is just
// 2x LDG.128 + 8 FMA + 1 coalesced store. Lanes with x0%4==3 and x1==x0+1
// need the element one past the window: handled by a predicated scalar
// fallback (~25% of lanes).

static constexpr int B = 4;
static constexpr int C = 64;
static constexpr int H = 384;
static constexpr int W = 512;
static constexpr int HW = H * W;
static constexpr int NPIX = B * H * W;

__device__ __forceinline__ void add_onehot(float4& v, int i, float w) {
    v.x += (i == 0) ? w : 0.0f;
    v.y += (i == 1) ? w : 0.0f;
    v.z += (i == 2) ? w : 0.0f;
    v.w += (i == 3) ? w : 0.0f;
}

__global__ __launch_bounds__(256) void resample2d_kernel(
    const float* __restrict__ in1,
    const float* __restrict__ flow,
    float* __restrict__ out)
{
    int idx = blockIdx.x * blockDim.x + threadIdx.x;
    if (idx >= NPIX) return;

    int x = idx & (W - 1);          // W = 512 = 2^9
    int t = idx >> 9;               // b*H + y
    int y = t % H;
    int b = t / H;

    int pix = y * W + x;
    const float* fptr = flow + (size_t)b * 2 * HW;
    float dx = fptr[pix];
    float dy = fptr[HW + pix];

    float xf = (float)x + dx;
    float yf = (float)y + dy;
    float x0f = floorf(xf);
    float y0f = floorf(yf);
    float a  = xf - x0f;            // frac x
    float bw = yf - y0f;            // frac y

    int x0i = (int)x0f;
    int y0i = (int)y0f;
    int x0 = min(max(x0i,     0), W - 1);
    int x1 = min(max(x0i + 1, 0), W - 1);
    int y0 = min(max(y0i,     0), H - 1);
    int y1 = min(max(y0i + 1, 0), H - 1);

    float w00 = (1.0f - a) * (1.0f - bw);
    float w10 = a * (1.0f - bw);
    float w01 = (1.0f - a) * bw;
    float w11 = a * bw;

    int xb  = x0 & ~3;              // aligned float4 window start within row
    int rem = x0 & 3;               // position of x0 inside window
    int d   = x1 - x0;              // 0 (clamped) or 1
    bool need_fb = (rem + d) > 3;   // x1 falls outside the window

    // Fold bilinear weights into one-hot weight vectors (computed once).
    float4 wv0 = make_float4(0.f, 0.f, 0.f, 0.f);  // row y0
    float4 wv1 = make_float4(0.f, 0.f, 0.f, 0.f);  // row y1
    add_onehot(wv0, rem, w00);
    add_onehot(wv1, rem, w01);
    int i2 = (rem + d) & 3;                        // masked; weight zeroed if fb
    float w10e = need_fb ? 0.0f : w10;
    float w11e = need_fb ? 0.0f : w11;
    add_onehot(wv0, i2, w10e);
    add_onehot(wv1, i2, w11e);

    const float* base = in1 + (size_t)b * C * HW;
    const float4* p0 = (const float4*)(base + y0 * W + xb);
    const float4* p1 = (const float4*)(base + y1 * W + xb);
    const float* pf0 = base + y0 * W + x1;   // fallback scalar addr (row y0)
    const float* pf1 = base + y1 * W + x1;   // fallback scalar addr (row y1)
    float* o = out + (size_t)b * C * HW + pix;

    constexpr int S4 = HW / 4;      // float4 stride between channels

    #pragma unroll 4
    for (int c = 0; c < C; ++c) {
        float4 q0 = __ldg(p0 + (size_t)c * S4);
        float4 q1 = __ldg(p1 + (size_t)c * S4);
        float r = q0.x * wv0.x + q0.y * wv0.y + q0.z * wv0.z + q0.w * wv0.w
                + q1.x * wv1.x + q1.y * wv1.y + q1.z * wv1.z + q1.w * wv1.w;
        if (need_fb) {
            r += w10 * __ldg(pf0 + (size_t)c * HW)
               + w11 * __ldg(pf1 + (size_t)c * HW);
        }
        o[(size_t)c * HW] = r;
    }
}

extern "C" void kernel_launch(void* const* d_in, const int* in_sizes, int n_in,
                              void* d_out, int out_size)
{
    const float* in1  = (const float*)d_in[0];
    const float* flow = (const float*)d_in[1];
    float*       out  = (float*)d_out;

    int threads = 256;
    int blocks = (NPIX + threads - 1) / threads;
    resample2d_kernel<<<blocks, threads>>>(in1, flow, out);
}